// round 1
// baseline (speedup 1.0000x reference)
#include <cuda_runtime.h>
#include <math_constants.h>

#define N_S   50000
#define N_P   10000
#define EN    320000
#define D_IN  512
#define D_OUT 256

// ---------------- scratch (static device globals; no allocation) ----------------
__device__ __align__(16) float g_w1[D_IN];
__device__ __align__(16) float g_w2[D_IN];
__device__ float g_s_src[N_S];
__device__ float g_s_dst[N_P];
__device__ float g_e[EN];
__device__ int   g_cnt[N_P];
__device__ int   g_off[N_P + 1];
__device__ int   g_cur[N_P];
__device__ int   g_eid[EN];
__device__ __align__(16) float g_agg[(size_t)N_P * D_IN];   // 20 MB

// ---------------- K0: zero per-dst edge counts ----------------
__global__ void k_zero_cnt() {
    int i = blockIdx.x * blockDim.x + threadIdx.x;
    if (i < N_P) g_cnt[i] = 0;
}

// ---------------- K1: fold attention vector through W: w1 = W^T a1, w2 = W^T a2 ----
__global__ void k_fold_w(const float* __restrict__ W, const float* __restrict__ aw) {
    int k = threadIdx.x;            // 0..511, one thread per input feature
    float a1 = 0.f, a2 = 0.f;
    #pragma unroll 8
    for (int d = 0; d < D_OUT; d++) {
        float w = W[d * D_IN + k];  // coalesced across warp
        a1 += w * aw[d];
        a2 += w * aw[D_OUT + d];
    }
    g_w1[k] = a1;
    g_w2[k] = a2;
}

// ---------------- K2: per-node scalar scores (warp per row) ----------------
__global__ void k_scores(const float* __restrict__ hs, const float* __restrict__ hp) {
    int gw   = (blockIdx.x * blockDim.x + threadIdx.x) >> 5;
    int lane = threadIdx.x & 31;
    if (gw >= N_S + N_P) return;
    const float4* row;
    const float4* wv;
    if (gw < N_S) {
        row = (const float4*)(hs + (size_t)gw * D_IN);
        wv  = (const float4*)g_w1;
    } else {
        row = (const float4*)(hp + (size_t)(gw - N_S) * D_IN);
        wv  = (const float4*)g_w2;
    }
    float acc = 0.f;
    #pragma unroll
    for (int i = lane; i < D_IN / 4; i += 32) {
        float4 a = row[i];
        float4 b = wv[i];
        acc += a.x * b.x + a.y * b.y + a.z * b.z + a.w * b.w;
    }
    #pragma unroll
    for (int o = 16; o; o >>= 1) acc += __shfl_xor_sync(0xffffffffu, acc, o);
    if (lane == 0) {
        if (gw < N_S) g_s_src[gw] = acc;
        else          g_s_dst[gw - N_S] = acc;
    }
}

// ---------------- K3: per-edge raw attention logit + dst histogram ----------------
__global__ void k_edges(const int* __restrict__ src, const int* __restrict__ dst) {
    int e = blockIdx.x * blockDim.x + threadIdx.x;
    if (e >= EN) return;
    int d = dst[e];
    float v = g_s_src[src[e]] + g_s_dst[d];
    v = (v > 0.f) ? v : 0.01f * v;      // leaky_relu, slope 0.01
    g_e[e] = v;
    atomicAdd(&g_cnt[d], 1);
}

// ---------------- K4: exclusive scan of counts -> CSR offsets (single block) ------
__global__ void k_scan() {
    __shared__ int sm[1024];
    __shared__ int s_carry;
    if (threadIdx.x == 0) s_carry = 0;
    __syncthreads();
    for (int base = 0; base < N_P; base += 1024) {
        int i = base + threadIdx.x;
        int v = (i < N_P) ? g_cnt[i] : 0;
        sm[threadIdx.x] = v;
        __syncthreads();
        #pragma unroll
        for (int o = 1; o < 1024; o <<= 1) {
            int t = (threadIdx.x >= o) ? sm[threadIdx.x - o] : 0;
            __syncthreads();
            sm[threadIdx.x] += t;
            __syncthreads();
        }
        int carry = s_carry;
        int incl  = sm[threadIdx.x] + carry;
        if (i < N_P) {
            g_off[i + 1] = incl;
            g_cur[i]     = incl - v;   // exclusive offset (scatter cursor)
        }
        if (threadIdx.x == 0 && base == 0) g_off[0] = 0;
        __syncthreads();
        if (threadIdx.x == 1023) s_carry = incl;
        __syncthreads();
    }
}

// ---------------- K5: scatter edge ids into CSR ----------------
__global__ void k_scatter(const int* __restrict__ dst) {
    int e = blockIdx.x * blockDim.x + threadIdx.x;
    if (e >= EN) return;
    int pos = atomicAdd(&g_cur[dst[e]], 1);
    g_eid[pos] = e;
}

// ---------------- K6: per-dst softmax + weighted gather-accumulate of h_s --------
// one block (128 threads) per dst node; acc = 4 floats/thread (512 total)
__global__ void k_aggregate(const float* __restrict__ hs, const int* __restrict__ src) {
    int p = blockIdx.x;
    int t = threadIdx.x;                       // 0..127
    int start = g_off[p];
    int cnt   = g_cnt[p];

    __shared__ float red[128];
    __shared__ int   ss[128];
    __shared__ float ws[128];

    // pass 1: max
    float lm = -CUDART_INF_F;
    for (int j = t; j < cnt; j += 128) lm = fmaxf(lm, g_e[g_eid[start + j]]);
    red[t] = lm;
    __syncthreads();
    #pragma unroll
    for (int o = 64; o; o >>= 1) {
        if (t < o) red[t] = fmaxf(red[t], red[t + o]);
        __syncthreads();
    }
    float m = red[0];
    __syncthreads();

    // pass 2: sum of exp
    float ls = 0.f;
    for (int j = t; j < cnt; j += 128) ls += __expf(g_e[g_eid[start + j]] - m);
    red[t] = ls;
    __syncthreads();
    #pragma unroll
    for (int o = 64; o; o >>= 1) {
        if (t < o) red[t] += red[t + o];
        __syncthreads();
    }
    float inv = (cnt > 0) ? (1.0f / red[0]) : 0.f;
    __syncthreads();

    // pass 3: weighted accumulation of gathered h_s rows
    float4 acc = make_float4(0.f, 0.f, 0.f, 0.f);
    for (int base = 0; base < cnt; base += 128) {
        int j = base + t;
        if (j < cnt) {
            int eid = g_eid[start + j];
            ss[t] = src[eid];
            ws[t] = __expf(g_e[eid] - m) * inv;
        }
        __syncthreads();
        int lim = min(128, cnt - base);
        for (int q = 0; q < lim; q++) {
            float w = ws[q];
            const float4* row = (const float4*)(hs + (size_t)ss[q] * D_IN);
            float4 v = __ldg(row + t);
            acc.x += w * v.x;
            acc.y += w * v.y;
            acc.z += w * v.z;
            acc.w += w * v.w;
        }
        __syncthreads();
    }
    ((float4*)(g_agg + (size_t)p * D_IN))[t] = acc;
}

// ---------------- K7: out = agg[M,K] @ W^T   (out[p,d] = dot(agg_p, W_d)) ---------
// 64x64 tile, 256 threads, 4x4 per thread, BK=16
__global__ void k_gemm(const float* __restrict__ W, float* __restrict__ out) {
    const int M = N_P, K = D_IN, N = D_OUT;
    __shared__ float As[16][64 + 4];
    __shared__ float Bs[16][64 + 4];

    int bm = blockIdx.x * 64;
    int bn = blockIdx.y * 64;
    int tx = threadIdx.x % 16;
    int ty = threadIdx.x / 16;

    int lrow  = threadIdx.x / 4;         // 0..63
    int lcol4 = (threadIdx.x % 4) * 4;   // 0,4,8,12

    float acc[4][4] = {};

    for (int k0 = 0; k0 < K; k0 += 16) {
        float4 av = make_float4(0.f, 0.f, 0.f, 0.f);
        int arow = bm + lrow;
        if (arow < M)
            av = *(const float4*)(g_agg + (size_t)arow * K + k0 + lcol4);
        As[lcol4 + 0][lrow] = av.x;
        As[lcol4 + 1][lrow] = av.y;
        As[lcol4 + 2][lrow] = av.z;
        As[lcol4 + 3][lrow] = av.w;

        float4 bv = *(const float4*)(W + (size_t)(bn + lrow) * K + k0 + lcol4);
        Bs[lcol4 + 0][lrow] = bv.x;
        Bs[lcol4 + 1][lrow] = bv.y;
        Bs[lcol4 + 2][lrow] = bv.z;
        Bs[lcol4 + 3][lrow] = bv.w;
        __syncthreads();

        #pragma unroll
        for (int k = 0; k < 16; k++) {
            float4 a4 = *(const float4*)&As[k][ty * 4];
            float4 b4 = *(const float4*)&Bs[k][tx * 4];
            acc[0][0] += a4.x * b4.x; acc[0][1] += a4.x * b4.y; acc[0][2] += a4.x * b4.z; acc[0][3] += a4.x * b4.w;
            acc[1][0] += a4.y * b4.x; acc[1][1] += a4.y * b4.y; acc[1][2] += a4.y * b4.z; acc[1][3] += a4.y * b4.w;
            acc[2][0] += a4.z * b4.x; acc[2][1] += a4.z * b4.y; acc[2][2] += a4.z * b4.z; acc[2][3] += a4.z * b4.w;
            acc[3][0] += a4.w * b4.x; acc[3][1] += a4.w * b4.y; acc[3][2] += a4.w * b4.z; acc[3][3] += a4.w * b4.w;
        }
        __syncthreads();
    }

    #pragma unroll
    for (int i = 0; i < 4; i++) {
        int r = bm + ty * 4 + i;
        if (r < M) {
            int c = bn + tx * 4;
            float4 o = make_float4(acc[i][0], acc[i][1], acc[i][2], acc[i][3]);
            *(float4*)(out + (size_t)r * N + c) = o;
        }
    }
}

// ---------------- launch ----------------
extern "C" void kernel_launch(void* const* d_in, const int* in_sizes, int n_in,
                              void* d_out, int out_size) {
    const float* hs  = (const float*)d_in[0];
    const float* hp  = (const float*)d_in[1];
    const float* W   = (const float*)d_in[2];
    const float* aw  = (const float*)d_in[3];
    const int*   src = (const int*)d_in[4];
    const int*   dst = (const int*)d_in[5];
    float*       out = (float*)d_out;

    k_zero_cnt<<<(N_P + 255) / 256, 256>>>();
    k_fold_w<<<1, D_IN>>>(W, aw);
    k_scores<<<((N_S + N_P) * 32 + 255) / 256, 256>>>(hs, hp);
    k_edges<<<(EN + 255) / 256, 256>>>(src, dst);
    k_scan<<<1, 1024>>>();
    k_scatter<<<(EN + 255) / 256, 256>>>(dst);
    k_aggregate<<<N_P, 128>>>(hs, src);
    k_gemm<<<dim3((N_P + 63) / 64, D_OUT / 64), 256>>>(W, out);
}

// round 2
// speedup vs baseline: 1.0921x; 1.0921x over previous
#include <cuda_runtime.h>
#include <cuda_bf16.h>
#include <math_constants.h>

#define N_S   50000
#define N_P   10000
#define EN    320000
#define D_IN  512
#define D_OUT 256
#define M_PAD 10112   // 79 * 128

// ---------------- scratch (static device globals; no allocation) ----------------
__device__ __align__(16) float g_w1[D_IN];
__device__ __align__(16) float g_w2[D_IN];
__device__ float g_s_src[N_S];
__device__ float g_s_dst[N_P];
__device__ float g_e[EN];
__device__ int   g_cnt[N_P];
__device__ int   g_off[N_P + 1];
__device__ int   g_cur[N_P];
__device__ int   g_eid[EN];
// aggregated h per dst, stored as bf16 hi/lo split (rows >= N_P stay zero-init)
__device__ __align__(16) __nv_bfloat16 g_agg_hi[(size_t)M_PAD * D_IN];
__device__ __align__(16) __nv_bfloat16 g_agg_lo[(size_t)M_PAD * D_IN];
// W in bf16 hi/lo split
__device__ __align__(16) __nv_bfloat16 g_W_hi[(size_t)D_OUT * D_IN];
__device__ __align__(16) __nv_bfloat16 g_W_lo[(size_t)D_OUT * D_IN];

__device__ __forceinline__ unsigned short bf_bits(__nv_bfloat16 h) {
    return *reinterpret_cast<unsigned short*>(&h);
}

// ---------------- K0: zero per-dst edge counts ----------------
__global__ void k_zero_cnt() {
    int i = blockIdx.x * blockDim.x + threadIdx.x;
    if (i < N_P) g_cnt[i] = 0;
}

// ---------------- K1: fold attention vector through W ----------------
// w1[k] = sum_d W[d][k] * a[d],  w2[k] = sum_d W[d][k] * a[D_OUT+d]
__global__ void k_fold_w(const float* __restrict__ W, const float* __restrict__ aw) {
    int k = blockIdx.x * 32 + threadIdx.x;   // 16 blocks x 32 threads = 512
    float a1 = 0.f, a2 = 0.f;
    #pragma unroll 8
    for (int d = 0; d < D_OUT; d++) {
        float w = W[d * D_IN + k];
        a1 += w * aw[d];
        a2 += w * aw[D_OUT + d];
    }
    g_w1[k] = a1;
    g_w2[k] = a2;
}

// ---------------- K1b: split W into bf16 hi/lo ----------------
__global__ void k_convw(const float* __restrict__ W) {
    int i = blockIdx.x * blockDim.x + threadIdx.x;  // D_OUT*D_IN = 131072
    float v = W[i];
    __nv_bfloat16 hi = __float2bfloat16_rn(v);
    float r = v - __bfloat162float(hi);
    g_W_hi[i] = hi;
    g_W_lo[i] = __float2bfloat16_rn(r);
}

// ---------------- K2: per-node scalar scores (warp per row) ----------------
__global__ void k_scores(const float* __restrict__ hs, const float* __restrict__ hp) {
    int gw   = (blockIdx.x * blockDim.x + threadIdx.x) >> 5;
    int lane = threadIdx.x & 31;
    if (gw >= N_S + N_P) return;
    const float4* row;
    const float4* wv;
    if (gw < N_S) {
        row = (const float4*)(hs + (size_t)gw * D_IN);
        wv  = (const float4*)g_w1;
    } else {
        row = (const float4*)(hp + (size_t)(gw - N_S) * D_IN);
        wv  = (const float4*)g_w2;
    }
    float acc = 0.f;
    #pragma unroll
    for (int i = lane; i < D_IN / 4; i += 32) {
        float4 a = row[i];
        float4 b = wv[i];
        acc += a.x * b.x + a.y * b.y + a.z * b.z + a.w * b.w;
    }
    #pragma unroll
    for (int o = 16; o; o >>= 1) acc += __shfl_xor_sync(0xffffffffu, acc, o);
    if (lane == 0) {
        if (gw < N_S) g_s_src[gw] = acc;
        else          g_s_dst[gw - N_S] = acc;
    }
}

// ---------------- K3: per-edge logit + dst histogram ----------------
__global__ void k_edges(const int* __restrict__ src, const int* __restrict__ dst) {
    int e = blockIdx.x * blockDim.x + threadIdx.x;
    if (e >= EN) return;
    int d = dst[e];
    float v = g_s_src[src[e]] + g_s_dst[d];
    v = (v > 0.f) ? v : 0.01f * v;      // leaky_relu slope 0.01
    g_e[e] = v;
    atomicAdd(&g_cnt[d], 1);
}

// ---------------- K4: exclusive scan of counts -> CSR offsets ----------------
// single block, 1024 threads; thread t scans 10 contiguous counts
__global__ void k_scan() {
    __shared__ int wsum[32];
    int t    = threadIdx.x;
    int lane = t & 31;
    int wid  = t >> 5;
    int base = t * 10;
    int incl_loc[10];
    int cnts[10];
    int tot = 0;
    if (t < 1000) {
        #pragma unroll
        for (int i = 0; i < 10; i++) {
            int c = g_cnt[base + i];
            cnts[i] = c;
            tot += c;
            incl_loc[i] = tot;
        }
    }
    // warp inclusive scan of per-thread totals
    int incl = tot;
    #pragma unroll
    for (int o = 1; o < 32; o <<= 1) {
        int v = __shfl_up_sync(0xffffffffu, incl, o);
        if (lane >= o) incl += v;
    }
    if (lane == 31) wsum[wid] = incl;
    __syncthreads();
    if (wid == 0) {
        int v = wsum[lane];
        #pragma unroll
        for (int o = 1; o < 32; o <<= 1) {
            int u = __shfl_up_sync(0xffffffffu, v, o);
            if (lane >= o) v += u;
        }
        wsum[lane] = v;
    }
    __syncthreads();
    int warpoff = (wid == 0) ? 0 : wsum[wid - 1];
    int texcl   = warpoff + incl - tot;       // exclusive prefix of this thread
    if (t < 1000) {
        #pragma unroll
        for (int i = 0; i < 10; i++) {
            int iv = texcl + incl_loc[i];
            g_off[base + i + 1] = iv;
            g_cur[base + i]     = iv - cnts[i];
        }
    }
    if (t == 0) g_off[0] = 0;
}

// ---------------- K5: scatter edge ids into CSR ----------------
__global__ void k_scatter(const int* __restrict__ dst) {
    int e = blockIdx.x * blockDim.x + threadIdx.x;
    if (e >= EN) return;
    int pos = atomicAdd(&g_cur[dst[e]], 1);
    g_eid[pos] = e;
}

// ---------------- K6: per-dst softmax + weighted gather-accumulate of h_s --------
__global__ void k_aggregate(const float* __restrict__ hs, const int* __restrict__ src) {
    int p = blockIdx.x;
    int t = threadIdx.x;                       // 0..127
    int start = g_off[p];
    int cnt   = g_cnt[p];

    __shared__ float red[128];
    __shared__ int   ss[128];
    __shared__ float ws[128];

    // pass 1: max
    float lm = -CUDART_INF_F;
    for (int j = t; j < cnt; j += 128) lm = fmaxf(lm, g_e[g_eid[start + j]]);
    red[t] = lm;
    __syncthreads();
    #pragma unroll
    for (int o = 64; o; o >>= 1) {
        if (t < o) red[t] = fmaxf(red[t], red[t + o]);
        __syncthreads();
    }
    float m = red[0];
    __syncthreads();

    // pass 2: sum of exp
    float ls = 0.f;
    for (int j = t; j < cnt; j += 128) ls += __expf(g_e[g_eid[start + j]] - m);
    red[t] = ls;
    __syncthreads();
    #pragma unroll
    for (int o = 64; o; o >>= 1) {
        if (t < o) red[t] += red[t + o];
        __syncthreads();
    }
    float inv = (cnt > 0) ? (1.0f / red[0]) : 0.f;
    __syncthreads();

    // pass 3: weighted accumulation of gathered h_s rows
    float4 acc = make_float4(0.f, 0.f, 0.f, 0.f);
    for (int base = 0; base < cnt; base += 128) {
        int j = base + t;
        if (j < cnt) {
            int eid = g_eid[start + j];
            ss[t] = src[eid];
            ws[t] = __expf(g_e[eid] - m) * inv;
        }
        __syncthreads();
        int lim = min(128, cnt - base);
        #pragma unroll 4
        for (int q = 0; q < lim; q++) {
            float w = ws[q];
            const float4* row = (const float4*)(hs + (size_t)ss[q] * D_IN);
            float4 v = __ldg(row + t);
            acc.x += w * v.x;
            acc.y += w * v.y;
            acc.z += w * v.z;
            acc.w += w * v.w;
        }
        __syncthreads();
    }

    // write bf16 hi/lo split (col = t*4 .. t*4+3)
    float vv[4] = {acc.x, acc.y, acc.z, acc.w};
    unsigned short hb[4], lb[4];
    #pragma unroll
    for (int i = 0; i < 4; i++) {
        __nv_bfloat16 hi = __float2bfloat16_rn(vv[i]);
        float r = vv[i] - __bfloat162float(hi);
        __nv_bfloat16 lo = __float2bfloat16_rn(r);
        hb[i] = bf_bits(hi);
        lb[i] = bf_bits(lo);
    }
    size_t obase = (size_t)p * D_IN + t * 4;
    uint2 hp2, lp2;
    hp2.x = (unsigned)hb[0] | ((unsigned)hb[1] << 16);
    hp2.y = (unsigned)hb[2] | ((unsigned)hb[3] << 16);
    lp2.x = (unsigned)lb[0] | ((unsigned)lb[1] << 16);
    lp2.y = (unsigned)lb[2] | ((unsigned)lb[3] << 16);
    *(uint2*)(g_agg_hi + obase) = hp2;
    *(uint2*)(g_agg_lo + obase) = lp2;
}

// ---------------- K7: out = agg @ W^T via bf16-split tensor-core MMA -------------
// block tile 128x128, 8 warps (4x2), warp tile 32x64, k-step 16
#define SMS 24   // smem row stride in bf16 elems (16 + 8 pad -> conflict-free)

__device__ __forceinline__ void mma_bf16(float d[4],
                                         unsigned a0, unsigned a1, unsigned a2, unsigned a3,
                                         unsigned b0, unsigned b1) {
    asm volatile(
        "mma.sync.aligned.m16n8k16.row.col.f32.bf16.bf16.f32 "
        "{%0,%1,%2,%3}, {%4,%5,%6,%7}, {%8,%9}, {%0,%1,%2,%3};\n"
        : "+f"(d[0]), "+f"(d[1]), "+f"(d[2]), "+f"(d[3])
        : "r"(a0), "r"(a1), "r"(a2), "r"(a3), "r"(b0), "r"(b1));
}

__global__ void __launch_bounds__(256, 1) k_gemm_mma(float* __restrict__ out) {
    __shared__ __align__(16) __nv_bfloat16 sAh[128 * SMS];
    __shared__ __align__(16) __nv_bfloat16 sAl[128 * SMS];
    __shared__ __align__(16) __nv_bfloat16 sBh[128 * SMS];
    __shared__ __align__(16) __nv_bfloat16 sBl[128 * SMS];

    const int bm = blockIdx.x * 128;
    const int bn = blockIdx.y * 128;
    const int tid  = threadIdx.x;
    const int lane = tid & 31;
    const int warp = tid >> 5;
    const int wm = (warp >> 1) * 32;   // 0,32,64,96
    const int wn = (warp & 1) * 64;    // 0,64
    const int g  = lane >> 2;          // 0..7
    const int tg = lane & 3;           // 0..3

    // gmem load mapping: 256 threads, each loads uint4 (8 bf16) per array
    const int lrow = tid >> 1;         // 0..127
    const int lc8  = (tid & 1) * 8;    // 0 or 8

    const __nv_bfloat16* gAh = g_agg_hi + (size_t)(bm + lrow) * D_IN + lc8;
    const __nv_bfloat16* gAl = g_agg_lo + (size_t)(bm + lrow) * D_IN + lc8;
    const __nv_bfloat16* gBh = g_W_hi   + (size_t)(bn + lrow) * D_IN + lc8;
    const __nv_bfloat16* gBl = g_W_lo   + (size_t)(bn + lrow) * D_IN + lc8;

    float d[2][8][4];
    #pragma unroll
    for (int mt = 0; mt < 2; mt++)
        #pragma unroll
        for (int nt = 0; nt < 8; nt++)
            #pragma unroll
            for (int i = 0; i < 4; i++) d[mt][nt][i] = 0.f;

    uint4 rah = *(const uint4*)gAh;
    uint4 ral = *(const uint4*)gAl;
    uint4 rbh = *(const uint4*)gBh;
    uint4 rbl = *(const uint4*)gBl;

    const int sidx = lrow * SMS + lc8;

    for (int ks = 0; ks < D_IN / 16; ks++) {
        *(uint4*)(sAh + sidx) = rah;
        *(uint4*)(sAl + sidx) = ral;
        *(uint4*)(sBh + sidx) = rbh;
        *(uint4*)(sBl + sidx) = rbl;
        __syncthreads();

        if (ks < D_IN / 16 - 1) {
            int koff = (ks + 1) * 16;
            rah = *(const uint4*)(gAh + koff);
            ral = *(const uint4*)(gAl + koff);
            rbh = *(const uint4*)(gBh + koff);
            rbl = *(const uint4*)(gBl + koff);
        }

        // load A fragments
        unsigned ah[2][4], al[2][4];
        #pragma unroll
        for (int mt = 0; mt < 2; mt++) {
            int r = wm + mt * 16;
            ah[mt][0] = *(const unsigned*)(sAh + (r + g)     * SMS + tg * 2);
            ah[mt][1] = *(const unsigned*)(sAh + (r + g + 8) * SMS + tg * 2);
            ah[mt][2] = *(const unsigned*)(sAh + (r + g)     * SMS + tg * 2 + 8);
            ah[mt][3] = *(const unsigned*)(sAh + (r + g + 8) * SMS + tg * 2 + 8);
            al[mt][0] = *(const unsigned*)(sAl + (r + g)     * SMS + tg * 2);
            al[mt][1] = *(const unsigned*)(sAl + (r + g + 8) * SMS + tg * 2);
            al[mt][2] = *(const unsigned*)(sAl + (r + g)     * SMS + tg * 2 + 8);
            al[mt][3] = *(const unsigned*)(sAl + (r + g + 8) * SMS + tg * 2 + 8);
        }

        #pragma unroll
        for (int nt = 0; nt < 8; nt++) {
            int rn = (wn + nt * 8 + g) * SMS + tg * 2;
            unsigned bh0 = *(const unsigned*)(sBh + rn);
            unsigned bh1 = *(const unsigned*)(sBh + rn + 8);
            unsigned bl0 = *(const unsigned*)(sBl + rn);
            unsigned bl1 = *(const unsigned*)(sBl + rn + 8);
            #pragma unroll
            for (int mt = 0; mt < 2; mt++) {
                mma_bf16(d[mt][nt], ah[mt][0], ah[mt][1], ah[mt][2], ah[mt][3], bh0, bh1);
                mma_bf16(d[mt][nt], ah[mt][0], ah[mt][1], ah[mt][2], ah[mt][3], bl0, bl1);
                mma_bf16(d[mt][nt], al[mt][0], al[mt][1], al[mt][2], al[mt][3], bh0, bh1);
            }
        }
        __syncthreads();
    }

    // epilogue
    #pragma unroll
    for (int mt = 0; mt < 2; mt++) {
        #pragma unroll
        for (int nt = 0; nt < 8; nt++) {
            int r0 = bm + wm + mt * 16 + g;
            int c  = bn + wn + nt * 8 + tg * 2;
            if (r0 < N_P) {
                float2 v0 = make_float2(d[mt][nt][0], d[mt][nt][1]);
                *(float2*)(out + (size_t)r0 * D_OUT + c) = v0;
            }
            if (r0 + 8 < N_P) {
                float2 v1 = make_float2(d[mt][nt][2], d[mt][nt][3]);
                *(float2*)(out + (size_t)(r0 + 8) * D_OUT + c) = v1;
            }
        }
    }
}

// ---------------- launch ----------------
extern "C" void kernel_launch(void* const* d_in, const int* in_sizes, int n_in,
                              void* d_out, int out_size) {
    const float* hs  = (const float*)d_in[0];
    const float* hp  = (const float*)d_in[1];
    const float* W   = (const float*)d_in[2];
    const float* aw  = (const float*)d_in[3];
    const int*   src = (const int*)d_in[4];
    const int*   dst = (const int*)d_in[5];
    float*       out = (float*)d_out;

    k_zero_cnt<<<(N_P + 255) / 256, 256>>>();
    k_fold_w<<<16, 32>>>(W, aw);
    k_convw<<<(D_OUT * D_IN) / 1024, 1024>>>(W);
    k_scores<<<((N_S + N_P) * 32 + 255) / 256, 256>>>(hs, hp);
    k_edges<<<(EN + 255) / 256, 256>>>(src, dst);
    k_scan<<<1, 1024>>>();
    k_scatter<<<(EN + 255) / 256, 256>>>(dst);
    k_aggregate<<<N_P, 128>>>(hs, src);
    k_gemm_mma<<<dim3(M_PAD / 128, D_OUT / 128), 256>>>(out);
}